// round 1
// baseline (speedup 1.0000x reference)
#include <cuda_runtime.h>
#include <cstdint>

#define Bq 900
#define Cc 80
#define QC 72000          // Bq*Cc
#define TOPK 300
#define KP 17
#define NTHREADS 512
#define CAP 4096
#define THRESH 2.3f

// out layout (floats): labels[B*300] | boxes[B*300*4] | scores[B*300] | kpts[B*300*17*2]

__device__ __forceinline__ unsigned long long make_key(float f, int idx) {
    unsigned int u = __float_as_uint(f);
    u = (u & 0x80000000u) ? ~u : (u | 0x80000000u);   // monotone-increasing map
    return ((unsigned long long)u << 32) | (unsigned int)(~idx); // smaller idx -> larger key
}

__global__ __launch_bounds__(NTHREADS, 2)
void dfine_post_kernel(const float* __restrict__ logits,
                       const float* __restrict__ boxes,
                       const float* __restrict__ kpts,
                       float* __restrict__ out, int B) {
    __shared__ unsigned long long cand[CAP];
    __shared__ int qbuf[TOPK];
    __shared__ int s_cnt, s_cut, s_n;

    const int tid = threadIdx.x;
    const int b   = blockIdx.x;

    const float4* lg4 = (const float4*)(logits + (size_t)b * QC);

    if (tid == 0) s_cnt = 0;
    __syncthreads();

    // ---- Pass 1: threshold filter (single streamed read of the row) ----
    for (int i = tid; i < QC / 4; i += NTHREADS) {
        float4 v = lg4[i];
        int base = i * 4;
        if (v.x > THRESH) { int p = atomicAdd(&s_cnt, 1); if (p < CAP) cand[p] = make_key(v.x, base + 0); }
        if (v.y > THRESH) { int p = atomicAdd(&s_cnt, 1); if (p < CAP) cand[p] = make_key(v.y, base + 1); }
        if (v.z > THRESH) { int p = atomicAdd(&s_cnt, 1); if (p < CAP) cand[p] = make_key(v.z, base + 2); }
        if (v.w > THRESH) { int p = atomicAdd(&s_cnt, 1); if (p < CAP) cand[p] = make_key(v.w, base + 3); }
    }
    __syncthreads();
    int cnt = s_cnt;

    // ---- Fallback (statistically never taken): exact radix-histogram select ----
    if (cnt < TOPK || cnt > CAP) {
        unsigned int* hist = (unsigned int*)cand;   // alias: hist consumed before cand reused
        for (int i = tid; i < 4096; i += NTHREADS) hist[i] = 0u;
        __syncthreads();
        const float* lg = logits + (size_t)b * QC;
        for (int i = tid; i < QC; i += NTHREADS) {
            unsigned int u = __float_as_uint(lg[i]);
            u = (u & 0x80000000u) ? ~u : (u | 0x80000000u);
            atomicAdd(&hist[u >> 20], 1u);
        }
        __syncthreads();
        if (tid == 0) {
            int acc = 0, cb = 0;
            for (int bin = 4095; bin >= 0; --bin) {
                acc += (int)hist[bin];
                if (acc >= TOPK) { cb = bin; break; }
            }
            s_cut = cb;
            s_cnt = 0;
        }
        __syncthreads();           // hist fully consumed; cand safe to overwrite
        int cut = s_cut;
        for (int i = tid; i < QC; i += NTHREADS) {
            float f = lg[i];
            unsigned int u = __float_as_uint(f);
            u = (u & 0x80000000u) ? ~u : (u | 0x80000000u);
            if ((int)(u >> 20) >= cut) {
                int p = atomicAdd(&s_cnt, 1);
                if (p < CAP) cand[p] = make_key(f, i);
            }
        }
        __syncthreads();
        cnt = s_cnt;
        if (cnt > CAP) cnt = CAP;
    }

    // ---- pad to power of two ----
    if (tid == 0) {
        int n = 1;
        while (n < cnt) n <<= 1;
        s_n = n;
    }
    __syncthreads();
    const int n = s_n;
    for (int i = cnt + tid; i < n; i += NTHREADS) cand[i] = 0ULL;
    __syncthreads();

    // ---- bitonic sort, descending ----
    for (int k = 2; k <= n; k <<= 1) {
        for (int j = k >> 1; j > 0; j >>= 1) {
            for (int i = tid; i < n; i += NTHREADS) {
                int ix = i ^ j;
                if (ix > i) {
                    unsigned long long a = cand[i], c = cand[ix];
                    bool desc = ((i & k) == 0);
                    if (desc ? (a < c) : (a > c)) { cand[i] = c; cand[ix] = a; }
                }
            }
            __syncthreads();
        }
    }

    // ---- emit labels / scores, stash qidx ----
    const size_t L1 = (size_t)B * TOPK;          // boxes offset
    const size_t L2 = L1 + (size_t)B * TOPK * 4; // scores offset
    const size_t L3 = L2 + (size_t)B * TOPK;     // kpts offset

    for (int t = tid; t < TOPK; t += NTHREADS) {
        unsigned long long key = cand[t];
        unsigned int u = (unsigned int)(key >> 32);
        u = (u & 0x80000000u) ? (u & 0x7FFFFFFFu) : ~u;
        float f = __uint_as_float(u);
        int idx = (int)(~(unsigned int)(key & 0xFFFFFFFFu));
        int lab = idx % Cc;
        int q   = idx / Cc;
        qbuf[t] = q;
        float score = 1.0f / (1.0f + __expf(-f));
        out[(size_t)b * TOPK + t]      = (float)lab;
        out[L2 + (size_t)b * TOPK + t] = score;
    }
    __syncthreads();

    // ---- gather boxes (float4) ----
    const float4* bx4 = (const float4*)boxes;
    float4* obx = (float4*)(out + L1);
    for (int t = tid; t < TOPK; t += NTHREADS) {
        int q = qbuf[t];
        obx[(size_t)b * TOPK + t] = bx4[(size_t)b * Bq + q];
    }

    // ---- gather keypoints (float2 per kp) ----
    const float2* kp2 = (const float2*)kpts;
    float2* okp = (float2*)(out + L3);
    for (int i = tid; i < TOPK * KP; i += NTHREADS) {
        int t = i / KP;
        int k = i % KP;
        int q = qbuf[t];
        okp[((size_t)b * TOPK + t) * KP + k] = kp2[((size_t)b * Bq + q) * KP + k];
    }
}

extern "C" void kernel_launch(void* const* d_in, const int* in_sizes, int n_in,
                              void* d_out, int out_size) {
    const float* logits = (const float*)d_in[0];   // [B,900,80]
    const float* boxes  = (const float*)d_in[1];   // [B,900,4]
    const float* kpts   = (const float*)d_in[2];   // [B,900,17,2]
    int B = in_sizes[0] / QC;
    dfine_post_kernel<<<B, NTHREADS>>>(logits, boxes, kpts, (float*)d_out, B);
}

// round 3
// speedup vs baseline: 1.3136x; 1.3136x over previous
#include <cuda_runtime.h>
#include <cstdint>

#define Bq 900
#define Cc 80
#define QC 72000          // Bq*Cc
#define TOPK 300
#define KP 17
#define NTHREADS 512
#define CAP 2048
#define THRESH 2.5f

// out layout (floats): labels[B*300] | boxes[B*300*4] | scores[B*300] | kpts[B*300*17*2]

__device__ __forceinline__ unsigned long long make_key(float f, int idx) {
    unsigned int u = __float_as_uint(f);
    u = (u & 0x80000000u) ? ~u : (u | 0x80000000u);   // monotone-increasing map
    return ((unsigned long long)u << 32) | (unsigned int)(~idx); // smaller idx -> larger key
}

// warp-aggregated shared append. MUST be called with the full warp converged.
__device__ __forceinline__ void wagg_append(bool pred, float v, int idx,
                                            unsigned long long* cand, int* cnt) {
    unsigned int m = __ballot_sync(0xFFFFFFFFu, pred);
    if (m == 0) return;                       // uniform: every lane sees same m
    int lane = threadIdx.x & 31;
    int leader = __ffs(m) - 1;
    int pos = 0;
    if (lane == leader) pos = atomicAdd(cnt, __popc(m));
    pos = __shfl_sync(0xFFFFFFFFu, pos, leader);
    if (pred) {
        int p = pos + __popc(m & ((1u << lane) - 1u));
        if (p < CAP) cand[p] = make_key(v, idx);
    }
}

__global__ __launch_bounds__(NTHREADS, 4)
void dfine_post_kernel(const float* __restrict__ logits,
                       const float* __restrict__ boxes,
                       const float* __restrict__ kpts,
                       float* __restrict__ out, int B) {
    __shared__ unsigned long long cand[CAP];   // 16KB; aliased as hist[4096] in fallback
    __shared__ int qbuf[TOPK];
    __shared__ int s_cnt, s_cut, s_n;

    const int tid = threadIdx.x;
    const int b   = blockIdx.x;

    const float4* lg4 = (const float4*)(logits + (size_t)b * QC);

    if (tid == 0) s_cnt = 0;
    __syncthreads();

    // ---- Pass 1: threshold filter, UNIFORM trip count (all warps fully converged) ----
    const int NIT = (QC / 4 + NTHREADS - 1) / NTHREADS;   // 36
    for (int it = 0; it < NIT; ++it) {
        int i = it * NTHREADS + tid;
        bool in = (i < QC / 4);
        float4 v = make_float4(0.f, 0.f, 0.f, 0.f);
        if (in) v = lg4[i];
        int base = i * 4;
        wagg_append(in && v.x > THRESH, v.x, base + 0, cand, &s_cnt);
        wagg_append(in && v.y > THRESH, v.y, base + 1, cand, &s_cnt);
        wagg_append(in && v.z > THRESH, v.z, base + 2, cand, &s_cnt);
        wagg_append(in && v.w > THRESH, v.w, base + 3, cand, &s_cnt);
    }
    __syncthreads();
    int cnt = s_cnt;

    // ---- Fallback (statistically never taken): exact radix-histogram select ----
    if (cnt < TOPK || cnt > CAP) {
        unsigned int* hist = (unsigned int*)cand;   // 4096 bins; consumed before cand reused
        for (int i = tid; i < 4096; i += NTHREADS) hist[i] = 0u;
        __syncthreads();
        const float* lg = logits + (size_t)b * QC;
        for (int i = tid; i < QC; i += NTHREADS) {
            unsigned int u = __float_as_uint(lg[i]);
            u = (u & 0x80000000u) ? ~u : (u | 0x80000000u);
            atomicAdd(&hist[u >> 20], 1u);
        }
        __syncthreads();
        if (tid == 0) {
            int acc = 0, cb = 0;
            for (int bin = 4095; bin >= 0; --bin) {
                acc += (int)hist[bin];
                if (acc >= TOPK) { cb = bin; break; }
            }
            s_cut = cb;
            s_cnt = 0;
        }
        __syncthreads();           // hist fully consumed; cand safe to overwrite
        int cut = s_cut;
        for (int i = tid; i < QC; i += NTHREADS) {
            float f = lg[i];
            unsigned int u = __float_as_uint(f);
            u = (u & 0x80000000u) ? ~u : (u | 0x80000000u);
            if ((int)(u >> 20) >= cut) {
                int p = atomicAdd(&s_cnt, 1);
                if (p < CAP) cand[p] = make_key(f, i);
            }
        }
        __syncthreads();
        cnt = s_cnt;
        if (cnt > CAP) cnt = CAP;
    }

    // ---- pad to power of two ----
    if (tid == 0) {
        int n = 1;
        while (n < cnt) n <<= 1;
        s_n = n;
    }
    __syncthreads();
    const int n = s_n;
    for (int i = cnt + tid; i < n; i += NTHREADS) cand[i] = 0ULL;
    __syncthreads();

    // ---- bitonic sort, descending ----
    for (int k = 2; k <= n; k <<= 1) {
        for (int j = k >> 1; j > 0; j >>= 1) {
            for (int i = tid; i < n; i += NTHREADS) {
                int ix = i ^ j;
                if (ix > i) {
                    unsigned long long a = cand[i], c = cand[ix];
                    bool desc = ((i & k) == 0);
                    if (desc ? (a < c) : (a > c)) { cand[i] = c; cand[ix] = a; }
                }
            }
            __syncthreads();
        }
    }

    // ---- emit labels / scores, stash qidx ----
    const size_t L1 = (size_t)B * TOPK;          // boxes offset
    const size_t L2 = L1 + (size_t)B * TOPK * 4; // scores offset
    const size_t L3 = L2 + (size_t)B * TOPK;     // kpts offset

    for (int t = tid; t < TOPK; t += NTHREADS) {
        unsigned long long key = cand[t];
        unsigned int u = (unsigned int)(key >> 32);
        u = (u & 0x80000000u) ? (u & 0x7FFFFFFFu) : ~u;
        float f = __uint_as_float(u);
        int idx = (int)(~(unsigned int)(key & 0xFFFFFFFFu));
        int lab = idx % Cc;
        int q   = idx / Cc;
        qbuf[t] = q;
        float score = 1.0f / (1.0f + __expf(-f));
        out[(size_t)b * TOPK + t]      = (float)lab;
        out[L2 + (size_t)b * TOPK + t] = score;
    }
    __syncthreads();

    // ---- gather boxes (float4) ----
    const float4* bx4 = (const float4*)boxes;
    float4* obx = (float4*)(out + L1);
    for (int t = tid; t < TOPK; t += NTHREADS) {
        int q = qbuf[t];
        obx[(size_t)b * TOPK + t] = bx4[(size_t)b * Bq + q];
    }

    // ---- gather keypoints (float2 per kp) ----
    const float2* kp2 = (const float2*)kpts;
    float2* okp = (float2*)(out + L3);
    for (int i = tid; i < TOPK * KP; i += NTHREADS) {
        int t = i / KP;
        int k = i % KP;
        int q = qbuf[t];
        okp[((size_t)b * TOPK + t) * KP + k] = kp2[((size_t)b * Bq + q) * KP + k];
    }
}

extern "C" void kernel_launch(void* const* d_in, const int* in_sizes, int n_in,
                              void* d_out, int out_size) {
    const float* logits = (const float*)d_in[0];   // [B,900,80]
    const float* boxes  = (const float*)d_in[1];   // [B,900,4]
    const float* kpts   = (const float*)d_in[2];   // [B,900,17,2]
    int B = in_sizes[0] / QC;
    dfine_post_kernel<<<B, NTHREADS>>>(logits, boxes, kpts, (float*)d_out, B);
}

// round 4
// speedup vs baseline: 1.4946x; 1.1378x over previous
#include <cuda_runtime.h>
#include <cstdint>

#define Bq 900
#define Cc 80
#define QC 72000          // Bq*Cc
#define NV4 18000         // QC/4
#define TOPK 300
#define KP 17
#define NTHREADS 512
#define CAP 2048
#define THRESH 2.5f

// out layout (floats): labels[B*300] | boxes[B*300*4] | scores[B*300] | kpts[B*300*17*2]

__device__ __forceinline__ unsigned long long make_key(float f, int idx) {
    unsigned int u = __float_as_uint(f);
    u = (u & 0x80000000u) ? ~u : (u | 0x80000000u);   // monotone-increasing map
    return ((unsigned long long)u << 32) | (unsigned int)(~idx); // smaller idx -> larger key
}

__device__ __forceinline__ void emit4(float4 v, int base,
                                      unsigned long long* cand, int* cnt) {
    if (v.x > THRESH) { int p = atomicAdd(cnt, 1); if (p < CAP) cand[p] = make_key(v.x, base + 0); }
    if (v.y > THRESH) { int p = atomicAdd(cnt, 1); if (p < CAP) cand[p] = make_key(v.y, base + 1); }
    if (v.z > THRESH) { int p = atomicAdd(cnt, 1); if (p < CAP) cand[p] = make_key(v.z, base + 2); }
    if (v.w > THRESH) { int p = atomicAdd(cnt, 1); if (p < CAP) cand[p] = make_key(v.w, base + 3); }
}

__device__ __forceinline__ float max4(float4 v) {
    return fmaxf(fmaxf(v.x, v.y), fmaxf(v.z, v.w));
}

__global__ __launch_bounds__(NTHREADS, 4)
void dfine_post_kernel(const float* __restrict__ logits,
                       const float* __restrict__ boxes,
                       const float* __restrict__ kpts,
                       float* __restrict__ out, int B) {
    __shared__ unsigned long long cand[CAP];   // 16KB; aliased as hist[4096] in fallback
    __shared__ int qbuf[TOPK];
    __shared__ int s_cnt, s_cut, s_n;

    const int tid = threadIdx.x;
    const int b   = blockIdx.x;

    const float4* lg4 = (const float4*)(logits + (size_t)b * QC);

    if (tid == 0) s_cnt = 0;
    __syncthreads();

    // ---- Pass 1: threshold filter, 4x unrolled for MLP (no warp intrinsics) ----
    const int NFULL = NV4 / (NTHREADS * 4);          // 8 full outer iters -> 16384 float4s
    for (int it = 0; it < NFULL; ++it) {
        int i = it * NTHREADS * 4 + tid;
        float4 v0 = lg4[i];
        float4 v1 = lg4[i + NTHREADS];
        float4 v2 = lg4[i + 2 * NTHREADS];
        float4 v3 = lg4[i + 3 * NTHREADS];
        float mx = fmaxf(fmaxf(max4(v0), max4(v1)), fmaxf(max4(v2), max4(v3)));
        if (mx > THRESH) {
            emit4(v0, 4 * i, cand, &s_cnt);
            emit4(v1, 4 * (i + NTHREADS), cand, &s_cnt);
            emit4(v2, 4 * (i + 2 * NTHREADS), cand, &s_cnt);
            emit4(v3, 4 * (i + 3 * NTHREADS), cand, &s_cnt);
        }
    }
    // tail: remaining float4s (ragged, plain predicated code — no sync intrinsics)
    for (int i = NFULL * NTHREADS * 4 + tid; i < NV4; i += NTHREADS) {
        float4 v = lg4[i];
        if (max4(v) > THRESH) emit4(v, 4 * i, cand, &s_cnt);
    }
    __syncthreads();
    int cnt = s_cnt;

    // ---- Fallback (statistically never taken): exact radix-histogram select ----
    if (cnt < TOPK || cnt > CAP) {
        unsigned int* hist = (unsigned int*)cand;   // 4096 bins; consumed before cand reused
        for (int i = tid; i < 4096; i += NTHREADS) hist[i] = 0u;
        __syncthreads();
        const float* lg = logits + (size_t)b * QC;
        for (int i = tid; i < QC; i += NTHREADS) {
            unsigned int u = __float_as_uint(lg[i]);
            u = (u & 0x80000000u) ? ~u : (u | 0x80000000u);
            atomicAdd(&hist[u >> 20], 1u);
        }
        __syncthreads();
        if (tid == 0) {
            int acc = 0, cb = 0;
            for (int bin = 4095; bin >= 0; --bin) {
                acc += (int)hist[bin];
                if (acc >= TOPK) { cb = bin; break; }
            }
            s_cut = cb;
            s_cnt = 0;
        }
        __syncthreads();           // hist fully consumed; cand safe to overwrite
        int cut = s_cut;
        for (int i = tid; i < QC; i += NTHREADS) {
            float f = lg[i];
            unsigned int u = __float_as_uint(f);
            u = (u & 0x80000000u) ? ~u : (u | 0x80000000u);
            if ((int)(u >> 20) >= cut) {
                int p = atomicAdd(&s_cnt, 1);
                if (p < CAP) cand[p] = make_key(f, i);
            }
        }
        __syncthreads();
        cnt = s_cnt;
        if (cnt > CAP) cnt = CAP;
    }

    // ---- sort descending ----
    if (cnt <= NTHREADS) {
        // register bitonic: 1 key/thread, n = 512
        unsigned long long K = (tid < cnt) ? cand[tid] : 0ULL;
        for (int k = 2; k <= NTHREADS; k <<= 1) {
            bool desc = ((tid & k) == 0);
            for (int j = k >> 1; j > 0; j >>= 1) {
                unsigned long long part;
                if (j >= 32) {
                    __syncthreads();          // prior stage's reads complete
                    cand[tid] = K;
                    __syncthreads();
                    part = cand[tid ^ j];
                } else {
                    part = __shfl_xor_sync(0xFFFFFFFFu, K, j);
                }
                bool keepMax = (desc == ((tid & j) == 0));
                if (keepMax ? (part > K) : (part < K)) K = part;
            }
        }
        __syncthreads();
        cand[tid] = K;
        __syncthreads();
    } else {
        // generic shared bitonic (rare: cnt in (512, 2048])
        if (tid == 0) {
            int n = 1;
            while (n < cnt) n <<= 1;
            s_n = n;
        }
        __syncthreads();
        const int n = s_n;
        for (int i = cnt + tid; i < n; i += NTHREADS) cand[i] = 0ULL;
        __syncthreads();
        for (int k = 2; k <= n; k <<= 1) {
            for (int j = k >> 1; j > 0; j >>= 1) {
                for (int i = tid; i < n; i += NTHREADS) {
                    int ix = i ^ j;
                    if (ix > i) {
                        unsigned long long a = cand[i], c = cand[ix];
                        bool desc = ((i & k) == 0);
                        if (desc ? (a < c) : (a > c)) { cand[i] = c; cand[ix] = a; }
                    }
                }
                __syncthreads();
            }
        }
    }

    // ---- emit labels / scores, stash qidx ----
    const size_t L1 = (size_t)B * TOPK;          // boxes offset
    const size_t L2 = L1 + (size_t)B * TOPK * 4; // scores offset
    const size_t L3 = L2 + (size_t)B * TOPK;     // kpts offset

    if (tid < TOPK) {
        unsigned long long key = cand[tid];
        unsigned int u = (unsigned int)(key >> 32);
        u = (u & 0x80000000u) ? (u & 0x7FFFFFFFu) : ~u;
        float f = __uint_as_float(u);
        int idx = (int)(~(unsigned int)(key & 0xFFFFFFFFu));
        int lab = idx % Cc;
        int q   = idx / Cc;
        qbuf[tid] = q;
        float score = 1.0f / (1.0f + __expf(-f));
        out[(size_t)b * TOPK + tid]      = (float)lab;
        out[L2 + (size_t)b * TOPK + tid] = score;
    }
    __syncthreads();

    // ---- gather boxes (float4) ----
    const float4* bx4 = (const float4*)boxes;
    float4* obx = (float4*)(out + L1);
    if (tid < TOPK) {
        int q = qbuf[tid];
        obx[(size_t)b * TOPK + tid] = bx4[(size_t)b * Bq + q];
    }

    // ---- gather keypoints (float2 per kp) ----
    const float2* kp2 = (const float2*)kpts;
    float2* okp = (float2*)(out + L3);
    for (int i = tid; i < TOPK * KP; i += NTHREADS) {
        int t = i / KP;
        int k = i % KP;
        int q = qbuf[t];
        okp[((size_t)b * TOPK + t) * KP + k] = kp2[((size_t)b * Bq + q) * KP + k];
    }
}

extern "C" void kernel_launch(void* const* d_in, const int* in_sizes, int n_in,
                              void* d_out, int out_size) {
    const float* logits = (const float*)d_in[0];   // [B,900,80]
    const float* boxes  = (const float*)d_in[1];   // [B,900,4]
    const float* kpts   = (const float*)d_in[2];   // [B,900,17,2]
    int B = in_sizes[0] / QC;
    dfine_post_kernel<<<B, NTHREADS>>>(logits, boxes, kpts, (float*)d_out, B);
}